// round 11
// baseline (speedup 1.0000x reference)
#include <cuda_runtime.h>
#include <cuda_fp16.h>
#include <cstdint>

#define N_NODES 50000
#define N_EDGES 800000
#define H1      128
#define H2      64
#define HB      1563                       // hist blocks
#define XB      1563                       // x-convert blocks
#define WB      96                         // W-transpose blocks
#define SCAT_B  1563                       // scatter blocks
#define SCAN_BLOCKS 49
#define NTILES  391                        // ceil(50000/128)
#define ABUF    34816                      // 128 rows * 272 B

// ---------------- scratch (no allocations allowed) ----------------
__device__ int    g_deg[N_NODES];
__device__ int    g_ptr[N_NODES + 1];
__device__ int    g_rank[N_EDGES];
__device__ int    g_srcs[N_EDGES];
__device__ int    g_bsum[64];
__device__ __half g_xh[N_NODES * 128];     // fp16 x
__device__ __half g_Wt1[256 * 128];        // [Wl1^T ; Wr1^T]  fp16, [n][k]
__device__ __half g_Wt2[128 * 128];        // [Wl2^T ; Wr2^T]  fp16, [n][k]
__device__ __half g_yh[N_NODES * H1];      // fp16 lin_l output (reused layer 2)
__device__ float  g_r1[N_NODES * H1];      // fp32 lin_r output (reused layer 2)
__device__ __half g_hh[N_NODES * H1];      // fp16 hidden h

// ---------------- PTX helpers ----------------
__device__ __forceinline__ void mma_f16(float* c, const uint32_t* a, const uint32_t* b) {
    asm volatile(
        "mma.sync.aligned.m16n8k16.row.col.f32.f16.f16.f32 "
        "{%0,%1,%2,%3}, {%4,%5,%6,%7}, {%8,%9}, {%0,%1,%2,%3};"
        : "+f"(c[0]), "+f"(c[1]), "+f"(c[2]), "+f"(c[3])
        : "r"(a[0]), "r"(a[1]), "r"(a[2]), "r"(a[3]),
          "r"(b[0]), "r"(b[1]));
}
#define LDSM_X4(r, addr) \
    asm volatile("ldmatrix.sync.aligned.m8n8.x4.shared.b16 {%0,%1,%2,%3}, [%4];" \
        : "=r"((r)[0]), "=r"((r)[1]), "=r"((r)[2]), "=r"((r)[3]) : "r"(addr))
__device__ __forceinline__ void cp16(uint32_t s, const void* g) {
    asm volatile("cp.async.cg.shared.global [%0], [%1], 16;" :: "r"(s), "l"(g));
}

// ---------------- fat prep: hist + x->fp16 + W transpose ----------------
__global__ __launch_bounds__(512) void k_fath(const int* __restrict__ dst,
                                              const float* __restrict__ x,
                                              const float* __restrict__ Wl1,
                                              const float* __restrict__ Wr1,
                                              const float* __restrict__ Wl2,
                                              const float* __restrict__ Wr2) {
    int b = blockIdx.x, t = threadIdx.x;
    if (b < HB) {
        int e = b * 512 + t;
        if (e < N_EDGES) g_rank[e] = atomicAdd(&g_deg[dst[e]], 1);
    } else if (b < HB + XB) {
        int chunk = (b - HB) * 512 + t;
        if (chunk < N_NODES * 16) {
            int i8 = chunk * 8;
            float4 v0 = *(const float4*)&x[i8];
            float4 v1 = *(const float4*)&x[i8 + 4];
            __half2 h0 = __floats2half2_rn(v0.x, v0.y);
            __half2 h1 = __floats2half2_rn(v0.z, v0.w);
            __half2 h2 = __floats2half2_rn(v1.x, v1.y);
            __half2 h3 = __floats2half2_rn(v1.z, v1.w);
            *(uint4*)&g_xh[i8] = make_uint4(*(uint32_t*)&h0, *(uint32_t*)&h1,
                                            *(uint32_t*)&h2, *(uint32_t*)&h3);
        }
    } else {
        int i = (b - HB - XB) * 512 + t;
        if (i < 256 * 128) {
            int n = i >> 7, k = i & 127;
            float w = (n < 128) ? Wl1[k * 128 + n] : Wr1[k * 128 + (n - 128)];
            g_Wt1[i] = __float2half_rn(w);
        } else {
            int j = i - 256 * 128;
            if (j < 128 * 128) {
                int n = j >> 7, k = j & 127;
                float w = (n < 64) ? Wl2[k * 64 + n] : Wr2[k * 64 + (n - 64)];
                g_Wt2[j] = __float2half_rn(w);
            }
        }
    }
}

// ---------------- scan ----------------
__global__ __launch_bounds__(1024) void k_scan_a() {
    __shared__ int s[1024];
    int t = threadIdx.x;
    int i = blockIdx.x * 1024 + t;
    int val = (i < N_NODES) ? g_deg[i] : 0;
    s[t] = val;
    __syncthreads();
#pragma unroll
    for (int off = 1; off < 1024; off <<= 1) {
        int v = (t >= off) ? s[t - off] : 0;
        __syncthreads();
        s[t] += v;
        __syncthreads();
    }
    if (i < N_NODES) g_ptr[i] = s[t] - val;
    if (t == 1023) g_bsum[blockIdx.x] = s[t];
}
__global__ __launch_bounds__(1024) void k_scan_c() {
    __shared__ int off_s;
    int t = threadIdx.x;
    if (t == 0) {
        int acc = 0;
        for (int b = 0; b < blockIdx.x; b++) acc += g_bsum[b];
        off_s = acc;
    }
    __syncthreads();
    int i = blockIdx.x * 1024 + t;
    if (i < N_NODES) g_ptr[i] += off_s;
    if (i == 0) g_ptr[N_NODES] = N_EDGES;
}

// ---------------- multi-tile GEMM: W staged once, A double-buffered ----------------
// smem: W [128][272B] @0, A bufs @34816 and @69632. Total 104448 B.
template <int M_OUT>
__device__ __forceinline__ void gemm_multi(__half* smh, int tile0, int tstride, int cw,
                                           const __half* __restrict__ A,
                                           const __half* __restrict__ Wt,
                                           __half* __restrict__ Y,
                                           float* __restrict__ R) {
    const int tid = threadIdx.x;
    uint32_t sbase = (uint32_t)__cvta_generic_to_shared(smh);
    const uint32_t sW = sbase;
    const uint32_t sA[2] = { sbase + ABUF, sbase + 2 * ABUF };
    __half* smA[2] = { smh + ABUF / 2, smh + ABUF };

    // stage W once + A(tile0), one commit group
    for (int i = tid; i < 2048; i += 512) {
        int j = i >> 4, c = i & 15;
        int srcrow = cw + ((j < 64) ? j : j + M_OUT - 64);
        cp16(sW + j * 272 + c * 16, &Wt[(size_t)srcrow * 128 + c * 8]);
    }
    {
        int row0 = tile0 * 128;
        for (int i = tid; i < 2048; i += 512) {
            int r = i >> 4, c = i & 15;
            int gr = row0 + r;
            if (gr < N_NODES) cp16(sA[0] + r * 272 + c * 16, &A[(size_t)gr * 128 + c * 8]);
            else *(uint4*)(smA[0] + (r * 136 + c * 8)) = make_uint4(0, 0, 0, 0);
        }
    }
    asm volatile("cp.async.commit_group;");

    const int wid  = tid >> 5;
    const int lane = tid & 31;
    const int wr0  = (wid & 3) * 32;
    const int wc0  = (wid >> 2) * 32;
    const int lrow = lane & 7;
    const uint32_t aOff = (uint32_t)((wr0 + lrow + ((lane >> 3) & 1) * 8) * 272
                                     + ((lane >> 4) * 8) * 2);
    const uint32_t bBase = sW + (uint32_t)((wc0 + lrow + ((lane >> 4) & 1) * 8) * 272
                                           + (((lane >> 3) & 1) * 8) * 2);
    const int gid = lane >> 2;
    const int tig = lane & 3;
    const bool isR = (wc0 >= 64);
    const int  wcl = wc0 & 63;

    int buf = 0;
    for (int ti = tile0; ti < NTILES; ti += tstride) {
        int next = ti + tstride;
        if (next < NTILES) {                         // prefetch A(next) into buf^1
            int row0 = next * 128;
            int nb = buf ^ 1;
            for (int i = tid; i < 2048; i += 512) {
                int r = i >> 4, c = i & 15;
                int gr = row0 + r;
                if (gr < N_NODES) cp16(sA[nb] + r * 272 + c * 16, &A[(size_t)gr * 128 + c * 8]);
                else *(uint4*)(smA[nb] + (r * 136 + c * 8)) = make_uint4(0, 0, 0, 0);
            }
            asm volatile("cp.async.commit_group;");
            asm volatile("cp.async.wait_group 1;" ::: "memory");
        } else {
            asm volatile("cp.async.wait_group 0;" ::: "memory");
        }
        __syncthreads();

        const uint32_t aBase = sA[buf] + aOff;
        float acc[2][4][4];
#pragma unroll
        for (int mt = 0; mt < 2; mt++)
#pragma unroll
            for (int nt = 0; nt < 4; nt++)
#pragma unroll
                for (int i = 0; i < 4; i++) acc[mt][nt][i] = 0.f;

#pragma unroll
        for (int ks = 0; ks < 8; ks++) {
            uint32_t a0[4], a1[4], b0[4], b1[4];
            LDSM_X4(a0, aBase + ks * 32);
            LDSM_X4(a1, aBase + 16 * 272 + ks * 32);
            LDSM_X4(b0, bBase + ks * 32);
            LDSM_X4(b1, bBase + 16 * 272 + ks * 32);
            mma_f16(acc[0][0], a0, &b0[0]); mma_f16(acc[0][1], a0, &b0[2]);
            mma_f16(acc[0][2], a0, &b1[0]); mma_f16(acc[0][3], a0, &b1[2]);
            mma_f16(acc[1][0], a1, &b0[0]); mma_f16(acc[1][1], a1, &b0[2]);
            mma_f16(acc[1][2], a1, &b1[0]); mma_f16(acc[1][3], a1, &b1[2]);
        }

        const int rowb = ti * 128;
#pragma unroll
        for (int mt = 0; mt < 2; mt++) {
            int r = rowb + wr0 + mt * 16 + gid;
#pragma unroll
            for (int nt = 0; nt < 4; nt++) {
                int c = cw + wcl + nt * 8 + 2 * tig;
                if (isR) {
                    if (r < N_NODES)
                        *(float2*)&R[(size_t)r * M_OUT + c] =
                            make_float2(acc[mt][nt][0], acc[mt][nt][1]);
                    if (r + 8 < N_NODES)
                        *(float2*)&R[(size_t)(r + 8) * M_OUT + c] =
                            make_float2(acc[mt][nt][2], acc[mt][nt][3]);
                } else {
                    if (r < N_NODES)
                        *(__half2*)&Y[(size_t)r * M_OUT + c] =
                            __floats2half2_rn(acc[mt][nt][0], acc[mt][nt][1]);
                    if (r + 8 < N_NODES)
                        *(__half2*)&Y[(size_t)(r + 8) * M_OUT + c] =
                            __floats2half2_rn(acc[mt][nt][2], acc[mt][nt][3]);
                }
            }
        }
        __syncthreads();   // protect buf^1 before next prefetch overwrites it
        buf ^= 1;
    }
}

// ---------------- fat kernel: scatter blocks + layer-1 GEMM blocks ----------------
__global__ __launch_bounds__(512, 2) void k_fat1(const int* __restrict__ src,
                                                 const int* __restrict__ dst,
                                                 __half* __restrict__ Y,
                                                 float* __restrict__ R) {
    extern __shared__ __half smh[];
    if (blockIdx.x < SCAT_B) {
        int e = blockIdx.x * 512 + threadIdx.x;
        if (e < N_EDGES)
            g_srcs[g_ptr[dst[e]] + g_rank[e]] = src[e];
        return;
    }
    int b = blockIdx.x - SCAT_B;          // [0, 296)
    int col = b / 148;                    // 0 or 1
    int tile0 = b % 148;
    gemm_multi<H1>(smh, tile0, 148, col * 64, g_xh, g_Wt1, Y, R);
}

// ---------------- layer-2 GEMM ----------------
__global__ __launch_bounds__(512, 2) void k_mma2(__half* __restrict__ Y,
                                                 float* __restrict__ R) {
    extern __shared__ __half smh[];
    gemm_multi<H2>(smh, blockIdx.x, 296, 0, g_hh, g_Wt2, Y, R);
}

// ---------------- gather-mean aggregation: coalesced idx + shfl + HADD2 ----------------
template <int COLS, bool RELU, typename OUT_T>
__global__ __launch_bounds__(256) void k_agg(const __half* __restrict__ y,
                                             const float* __restrict__ r,
                                             const float* __restrict__ bias,
                                             OUT_T* __restrict__ out) {
    int gw   = (blockIdx.x * blockDim.x + threadIdx.x) >> 5;
    int lane = threadIdx.x & 31;
    if (gw >= N_NODES) return;

    int p0 = g_ptr[gw];
    int p1 = g_ptr[gw + 1];
    float inv = 1.0f / (float)max(p1 - p0, 1);
    const __half2 hz = __float2half2_rn(0.0f);

    if (COLS == 128) {
        const int c = lane * 4;
        float4 a0 = make_float4(0.f, 0.f, 0.f, 0.f);
        for (int base = p0; base < p1; base += 32) {
            int cnt = min(32, p1 - base);
            int myi = base + lane;
            int sidx = g_srcs[(myi < p1) ? myi : (p1 - 1)];
            int e = 0;
            for (; e + 8 <= cnt; e += 8) {
                int ss[8];
#pragma unroll
                for (int q = 0; q < 8; q++) ss[q] = __shfl_sync(0xffffffffu, sidx, e + q);
                uint2 u[8];
#pragma unroll
                for (int q = 0; q < 8; q++)
                    u[q] = __ldg((const uint2*)&y[(size_t)ss[q] * 128 + c]);
                __half2 hx0 = hz, hy0 = hz, hx1 = hz, hy1 = hz;
#pragma unroll
                for (int q = 0; q < 4; q++) {
                    hx0 = __hadd2(hx0, *(__half2*)&u[q].x);
                    hy0 = __hadd2(hy0, *(__half2*)&u[q].y);
                }
#pragma unroll
                for (int q = 4; q < 8; q++) {
                    hx1 = __hadd2(hx1, *(__half2*)&u[q].x);
                    hy1 = __hadd2(hy1, *(__half2*)&u[q].y);
                }
                float2 f;
                f = __half22float2(hx0); a0.x += f.x; a0.y += f.y;
                f = __half22float2(hy0); a0.z += f.x; a0.w += f.y;
                f = __half22float2(hx1); a0.x += f.x; a0.y += f.y;
                f = __half22float2(hy1); a0.z += f.x; a0.w += f.y;
            }
            if (e < cnt) {
                __half2 hx0 = hz, hy0 = hz, hx1 = hz, hy1 = hz;
                int n = 0;
                for (; e < cnt; e++, n++) {
                    int s = __shfl_sync(0xffffffffu, sidx, e);
                    uint2 u = __ldg((const uint2*)&y[(size_t)s * 128 + c]);
                    if (n & 1) {
                        hx1 = __hadd2(hx1, *(__half2*)&u.x);
                        hy1 = __hadd2(hy1, *(__half2*)&u.y);
                    } else {
                        hx0 = __hadd2(hx0, *(__half2*)&u.x);
                        hy0 = __hadd2(hy0, *(__half2*)&u.y);
                    }
                }
                float2 f;
                f = __half22float2(hx0); a0.x += f.x; a0.y += f.y;
                f = __half22float2(hy0); a0.z += f.x; a0.w += f.y;
                f = __half22float2(hx1); a0.x += f.x; a0.y += f.y;
                f = __half22float2(hy1); a0.z += f.x; a0.w += f.y;
            }
        }
        float4 rb = *(const float4*)&r[(size_t)gw * 128 + c];
        float4 bb = __ldg((const float4*)&bias[c]);
        float4 o;
        o.x = fmaf(a0.x, inv, bb.x + rb.x);
        o.y = fmaf(a0.y, inv, bb.y + rb.y);
        o.z = fmaf(a0.z, inv, bb.z + rb.z);
        o.w = fmaf(a0.w, inv, bb.w + rb.w);
        if (RELU) {
            o.x = fmaxf(o.x, 0.f); o.y = fmaxf(o.y, 0.f);
            o.z = fmaxf(o.z, 0.f); o.w = fmaxf(o.w, 0.f);
        }
        if (sizeof(OUT_T) == 2) {
            __half2 h0 = __floats2half2_rn(o.x, o.y);
            __half2 h1 = __floats2half2_rn(o.z, o.w);
            *(uint2*)&((__half*)out)[(size_t)gw * 128 + c] =
                make_uint2(*(uint32_t*)&h0, *(uint32_t*)&h1);
        } else {
            *(float4*)&((float*)out)[(size_t)gw * 128 + c] = o;
        }
    } else {
        const int c = lane * 2;
        float2 a0 = make_float2(0.f, 0.f);
        for (int base = p0; base < p1; base += 32) {
            int cnt = min(32, p1 - base);
            int myi = base + lane;
            int sidx = g_srcs[(myi < p1) ? myi : (p1 - 1)];
            int e = 0;
            for (; e + 8 <= cnt; e += 8) {
                int ss[8];
#pragma unroll
                for (int q = 0; q < 8; q++) ss[q] = __shfl_sync(0xffffffffu, sidx, e + q);
                __half2 v[8];
#pragma unroll
                for (int q = 0; q < 8; q++)
                    v[q] = __ldg((const __half2*)&y[(size_t)ss[q] * 64 + c]);
                __half2 h0 = hz, h1 = hz;
#pragma unroll
                for (int q = 0; q < 4; q++) h0 = __hadd2(h0, v[q]);
#pragma unroll
                for (int q = 4; q < 8; q++) h1 = __hadd2(h1, v[q]);
                float2 f;
                f = __half22float2(h0); a0.x += f.x; a0.y += f.y;
                f = __half22float2(h1); a0.x += f.x; a0.y += f.y;
            }
            if (e < cnt) {
                __half2 h0 = hz, h1 = hz;
                int n = 0;
                for (; e < cnt; e++, n++) {
                    int s = __shfl_sync(0xffffffffu, sidx, e);
                    __half2 v = __ldg((const __half2*)&y[(size_t)s * 64 + c]);
                    if (n & 1) h1 = __hadd2(h1, v);
                    else       h0 = __hadd2(h0, v);
                }
                float2 f;
                f = __half22float2(h0); a0.x += f.x; a0.y += f.y;
                f = __half22float2(h1); a0.x += f.x; a0.y += f.y;
            }
        }
        float2 rb = *(const float2*)&r[(size_t)gw * 64 + c];
        float2 bb = __ldg((const float2*)&bias[c]);
        float2 o;
        o.x = fmaf(a0.x, inv, bb.x + rb.x);
        o.y = fmaf(a0.y, inv, bb.y + rb.y);
        if (RELU) { o.x = fmaxf(o.x, 0.f); o.y = fmaxf(o.y, 0.f); }
        if (sizeof(OUT_T) == 2) {
            *(__half2*)&((__half*)out)[(size_t)gw * 64 + c] =
                __floats2half2_rn(o.x, o.y);
        } else {
            *(float2*)&((float*)out)[(size_t)gw * 64 + c] = o;
        }
    }
}

// ---------------- launch ----------------
extern "C" void kernel_launch(void* const* d_in, const int* in_sizes, int n_in,
                              void* d_out, int out_size) {
    const float* x   = (const float*)d_in[0];
    const float* Wl1 = (const float*)d_in[1];
    const float* bl1 = (const float*)d_in[2];
    const float* Wr1 = (const float*)d_in[3];
    const float* Wl2 = (const float*)d_in[4];
    const float* bl2 = (const float*)d_in[5];
    const float* Wr2 = (const float*)d_in[6];
    const int*   ei  = (const int*)d_in[7];
    const int* src = ei;
    const int* dst = ei + N_EDGES;
    float* out = (float*)d_out;

    __half *yhp, *hhp;
    float* r1p;
    int* degp;
    cudaGetSymbolAddress((void**)&yhp, g_yh);
    cudaGetSymbolAddress((void**)&hhp, g_hh);
    cudaGetSymbolAddress((void**)&r1p, g_r1);
    cudaGetSymbolAddress((void**)&degp, g_deg);

    constexpr int SMEM = 3 * ABUF;   // 104448 B
    cudaFuncSetAttribute(k_fat1,
                         cudaFuncAttributeMaxDynamicSharedMemorySize, SMEM);
    cudaFuncSetAttribute(k_mma2,
                         cudaFuncAttributeMaxDynamicSharedMemorySize, SMEM);

    cudaMemsetAsync(degp, 0, N_NODES * sizeof(int));
    k_fath  <<<HB + XB + WB, 512>>>(dst, x, Wl1, Wr1, Wl2, Wr2);
    k_scan_a<<<SCAN_BLOCKS, 1024>>>();
    k_scan_c<<<SCAN_BLOCKS, 1024>>>();

    // scatter + layer-1 GEMM fused launch (296 multi-tile GEMM CTAs)
    k_fat1<<<SCAT_B + 296, 512, SMEM>>>(src, dst, yhp, r1p);
    k_agg<128, true, __half><<<(N_NODES + 7) / 8, 256>>>(yhp, r1p, bl1, hhp);

    // layer 2 (296 multi-tile GEMM CTAs)
    k_mma2<<<296, 512, SMEM>>>(yhp, r1p);
    k_agg<64, false, float><<<(N_NODES + 7) / 8, 256>>>(yhp, r1p, bl2, out);
}

// round 12
// speedup vs baseline: 1.0975x; 1.0975x over previous
#include <cuda_runtime.h>
#include <cuda_fp16.h>
#include <cstdint>

#define N_NODES 50000
#define N_EDGES 800000
#define H1      128
#define H2      64
#define HB      1563                       // hist blocks (800000/512)
#define XB      1563                       // x-convert blocks
#define WB      96                         // W-transpose blocks
#define SCAT_B  1563                       // scatter blocks
#define GEMM1_B 782                        // layer-1 GEMM blocks (391 tiles x 2 cols)
#define SCAN_BLOCKS 49

// ---------------- scratch (no allocations allowed) ----------------
__device__ int    g_deg[N_NODES];
__device__ int    g_ptr[N_NODES + 1];
__device__ int    g_rank[N_EDGES];
__device__ int    g_srcs[N_EDGES];
__device__ int    g_bsum[64];
__device__ int    g_flag[64];
__device__ __half g_xh[N_NODES * 128];     // fp16 x
__device__ __half g_Wt1[256 * 128];        // [Wl1^T ; Wr1^T]  fp16, [n][k]
__device__ __half g_Wt2[128 * 128];        // [Wl2^T ; Wr2^T]  fp16, [n][k]
__device__ __half g_yh[N_NODES * H1];      // fp16 lin_l output (reused layer 2)
__device__ float  g_r1[N_NODES * H1];      // fp32 lin_r output (reused layer 2)
__device__ __half g_hh[N_NODES * H1];      // fp16 hidden h

// ---------------- PTX helpers ----------------
__device__ __forceinline__ void mma_f16(float* c, const uint32_t* a, const uint32_t* b) {
    asm volatile(
        "mma.sync.aligned.m16n8k16.row.col.f32.f16.f16.f32 "
        "{%0,%1,%2,%3}, {%4,%5,%6,%7}, {%8,%9}, {%0,%1,%2,%3};"
        : "+f"(c[0]), "+f"(c[1]), "+f"(c[2]), "+f"(c[3])
        : "r"(a[0]), "r"(a[1]), "r"(a[2]), "r"(a[3]),
          "r"(b[0]), "r"(b[1]));
}
#define LDSM_X4(r, addr) \
    asm volatile("ldmatrix.sync.aligned.m8n8.x4.shared.b16 {%0,%1,%2,%3}, [%4];" \
        : "=r"((r)[0]), "=r"((r)[1]), "=r"((r)[2]), "=r"((r)[3]) : "r"(addr))
__device__ __forceinline__ void cp16(uint32_t s, const void* g) {
    asm volatile("cp.async.cg.shared.global [%0], [%1], 16;" :: "r"(s), "l"(g));
}
__device__ __forceinline__ void cp_commit_wait() {
    asm volatile("cp.async.commit_group;");
    asm volatile("cp.async.wait_group 0;" ::: "memory");
}

// ---------------- fat prep: hist + x->fp16 + W transpose + flag zero ----------------
__global__ __launch_bounds__(512) void k_fath(const int* __restrict__ dst,
                                              const float* __restrict__ x,
                                              const float* __restrict__ Wl1,
                                              const float* __restrict__ Wr1,
                                              const float* __restrict__ Wl2,
                                              const float* __restrict__ Wr2) {
    int b = blockIdx.x, t = threadIdx.x;
    if (b < HB) {
        int e = b * 512 + t;
        if (e < N_EDGES) g_rank[e] = atomicAdd(&g_deg[dst[e]], 1);
    } else if (b < HB + XB) {
        int chunk = (b - HB) * 512 + t;
        if (chunk < N_NODES * 16) {          // 8 floats per chunk
            int i8 = chunk * 8;
            float4 v0 = *(const float4*)&x[i8];
            float4 v1 = *(const float4*)&x[i8 + 4];
            __half2 h0 = __floats2half2_rn(v0.x, v0.y);
            __half2 h1 = __floats2half2_rn(v0.z, v0.w);
            __half2 h2 = __floats2half2_rn(v1.x, v1.y);
            __half2 h3 = __floats2half2_rn(v1.z, v1.w);
            *(uint4*)&g_xh[i8] = make_uint4(*(uint32_t*)&h0, *(uint32_t*)&h1,
                                            *(uint32_t*)&h2, *(uint32_t*)&h3);
        }
    } else {
        if (b == HB + XB && t < 64) g_flag[t] = 0;   // reset scan flags each call
        int i = (b - HB - XB) * 512 + t;
        if (i < 256 * 128) {
            int n = i >> 7, k = i & 127;
            float w = (n < 128) ? Wl1[k * 128 + n] : Wr1[k * 128 + (n - 128)];
            g_Wt1[i] = __float2half_rn(w);
        } else {
            int j = i - 256 * 128;
            if (j < 128 * 128) {
                int n = j >> 7, k = j & 127;
                float w = (n < 64) ? Wl2[k * 64 + n] : Wr2[k * 64 + (n - 64)];
                g_Wt2[j] = __float2half_rn(w);
            }
        }
    }
}

// ---------------- single-launch scan with PARALLEL lookback ----------------
// 49 blocks (sole launch, all co-resident). Also zeroes g_deg for the next call.
__global__ __launch_bounds__(1024) void k_scan() {
    __shared__ int s[1024];
    __shared__ int off_s;
    const int t = threadIdx.x, b = blockIdx.x;
    const int i = b * 1024 + t;
    int val = 0;
    if (i < N_NODES) {
        val = g_deg[i];
        g_deg[i] = 0;                      // self-zero for next call's histogram
    }
    s[t] = val;
    if (t == 0) off_s = 0;
    __syncthreads();
#pragma unroll
    for (int off = 1; off < 1024; off <<= 1) {
        int v = (t >= off) ? s[t - off] : 0;
        __syncthreads();
        s[t] += v;
        __syncthreads();
    }
    if (t == 1023) {                       // publish block total
        g_bsum[b] = s[1023];
        __threadfence();
        atomicExch(&g_flag[b], 1);
    }
    if (t < b) {                           // parallel lookback: one poll each
        while (atomicAdd(&g_flag[t], 0) == 0) {}
        atomicAdd(&off_s, atomicAdd(&g_bsum[t], 0));
    }
    __syncthreads();
    if (i < N_NODES) g_ptr[i] = off_s + s[t] - val;
    if (i == 0) g_ptr[N_NODES] = N_EDGES;
}

// ---------------- GEMM body: cp.async staging + ldmatrix + fp16 mma (R8/R10) ----------------
template <int M_OUT>
__device__ __forceinline__ void gemm_body(__half* smh,
                                          int row0, int cw,
                                          const __half* __restrict__ A,
                                          const __half* __restrict__ Wt,
                                          __half* __restrict__ Y,
                                          float* __restrict__ R) {
    const int tid = threadIdx.x;
    uint32_t sbase = (uint32_t)__cvta_generic_to_shared(smh);
    const uint32_t sA = sbase;
    const uint32_t sW = sbase + 128 * 272;

    for (int i = tid; i < 2048; i += 512) {
        int r = i >> 4, c = i & 15;
        int gr = row0 + r;
        uint32_t d = sA + r * 272 + c * 16;
        if (gr < N_NODES) cp16(d, &A[(size_t)gr * 128 + c * 8]);
        else *(uint4*)(smh + (r * 136 + c * 8)) = make_uint4(0, 0, 0, 0);
    }
    for (int i = tid; i < 2048; i += 512) {
        int j = i >> 4, c = i & 15;
        int srcrow = cw + ((j < 64) ? j : j + M_OUT - 64);
        cp16(sW + j * 272 + c * 16, &Wt[(size_t)srcrow * 128 + c * 8]);
    }
    cp_commit_wait();
    __syncthreads();

    const int wid  = tid >> 5;
    const int lane = tid & 31;
    const int wr0  = (wid & 3) * 32;
    const int wc0  = (wid >> 2) * 32;
    const int lrow = lane & 7;

    const uint32_t aBase = sA + (uint32_t)((wr0 + lrow + ((lane >> 3) & 1) * 8) * 272
                                           + ((lane >> 4) * 8) * 2);
    const uint32_t bBase = sW + (uint32_t)((wc0 + lrow + ((lane >> 4) & 1) * 8) * 272
                                           + (((lane >> 3) & 1) * 8) * 2);

    float acc[2][4][4];
#pragma unroll
    for (int mt = 0; mt < 2; mt++)
#pragma unroll
        for (int nt = 0; nt < 4; nt++)
#pragma unroll
            for (int i = 0; i < 4; i++) acc[mt][nt][i] = 0.f;

#pragma unroll
    for (int ks = 0; ks < 8; ks++) {
        uint32_t a0[4], a1[4], b0[4], b1[4];
        LDSM_X4(a0, aBase + ks * 32);
        LDSM_X4(a1, aBase + 16 * 272 + ks * 32);
        LDSM_X4(b0, bBase + ks * 32);
        LDSM_X4(b1, bBase + 16 * 272 + ks * 32);
        mma_f16(acc[0][0], a0, &b0[0]); mma_f16(acc[0][1], a0, &b0[2]);
        mma_f16(acc[0][2], a0, &b1[0]); mma_f16(acc[0][3], a0, &b1[2]);
        mma_f16(acc[1][0], a1, &b0[0]); mma_f16(acc[1][1], a1, &b0[2]);
        mma_f16(acc[1][2], a1, &b1[0]); mma_f16(acc[1][3], a1, &b1[2]);
    }

    const int gid = lane >> 2;
    const int tig = lane & 3;
    const bool isR = (wc0 >= 64);
    const int  wcl = wc0 & 63;
#pragma unroll
    for (int mt = 0; mt < 2; mt++) {
        int r = row0 + wr0 + mt * 16 + gid;
#pragma unroll
        for (int nt = 0; nt < 4; nt++) {
            int c = cw + wcl + nt * 8 + 2 * tig;
            if (isR) {
                if (r < N_NODES)
                    *(float2*)&R[(size_t)r * M_OUT + c] =
                        make_float2(acc[mt][nt][0], acc[mt][nt][1]);
                if (r + 8 < N_NODES)
                    *(float2*)&R[(size_t)(r + 8) * M_OUT + c] =
                        make_float2(acc[mt][nt][2], acc[mt][nt][3]);
            } else {
                if (r < N_NODES)
                    *(__half2*)&Y[(size_t)r * M_OUT + c] =
                        __floats2half2_rn(acc[mt][nt][0], acc[mt][nt][1]);
                if (r + 8 < N_NODES)
                    *(__half2*)&Y[(size_t)(r + 8) * M_OUT + c] =
                        __floats2half2_rn(acc[mt][nt][2], acc[mt][nt][3]);
            }
        }
    }
}

// ---------------- fat kernel: layer-1 GEMM blocks FIRST, then scatter blocks ----------------
__global__ __launch_bounds__(512, 2) void k_fat1(const int* __restrict__ src,
                                                 const int* __restrict__ dst,
                                                 __half* __restrict__ Y,
                                                 float* __restrict__ R) {
    extern __shared__ __half smh[];
    if (blockIdx.x < GEMM1_B) {
        int b = blockIdx.x;
        gemm_body<H1>(smh, (b >> 1) * 128, (b & 1) * 64, g_xh, g_Wt1, Y, R);
        return;
    }
    int e = (blockIdx.x - GEMM1_B) * 512 + threadIdx.x;
    if (e < N_EDGES)
        g_srcs[g_ptr[dst[e]] + g_rank[e]] = src[e];
}

// ---------------- layer-2 GEMM ----------------
__global__ __launch_bounds__(512, 2) void k_mma2(__half* __restrict__ Y,
                                                 float* __restrict__ R) {
    extern __shared__ __half smh[];
    gemm_body<H2>(smh, blockIdx.x * 128, 0, g_hh, g_Wt2, Y, R);
}

// ---------------- gather-mean aggregation: HADD2 group accumulation (R10) ----------------
template <int COLS, bool RELU, typename OUT_T>
__global__ __launch_bounds__(256) void k_agg(const __half* __restrict__ y,
                                             const float* __restrict__ r,
                                             const float* __restrict__ bias,
                                             OUT_T* __restrict__ out) {
    int gw   = (blockIdx.x * blockDim.x + threadIdx.x) >> 5;
    int lane = threadIdx.x & 31;
    if (gw >= N_NODES) return;

    int p0 = g_ptr[gw];
    int p1 = g_ptr[gw + 1];
    float inv = 1.0f / (float)max(p1 - p0, 1);
    const __half2 hz = __float2half2_rn(0.0f);

    if (COLS == 128) {
        const int c = lane * 4;
        float4 a0 = make_float4(0.f, 0.f, 0.f, 0.f);
        int j = p0;
        for (; j + 8 <= p1; j += 8) {
            int ss[8];
#pragma unroll
            for (int q = 0; q < 8; q++) ss[q] = __ldg(&g_srcs[j + q]);
            uint2 u[8];
#pragma unroll
            for (int q = 0; q < 8; q++)
                u[q] = __ldg((const uint2*)&y[(size_t)ss[q] * 128 + c]);
            __half2 hx0 = hz, hy0 = hz, hx1 = hz, hy1 = hz;
#pragma unroll
            for (int q = 0; q < 4; q++) {
                hx0 = __hadd2(hx0, *(__half2*)&u[q].x);
                hy0 = __hadd2(hy0, *(__half2*)&u[q].y);
            }
#pragma unroll
            for (int q = 4; q < 8; q++) {
                hx1 = __hadd2(hx1, *(__half2*)&u[q].x);
                hy1 = __hadd2(hy1, *(__half2*)&u[q].y);
            }
            float2 f;
            f = __half22float2(hx0); a0.x += f.x; a0.y += f.y;
            f = __half22float2(hy0); a0.z += f.x; a0.w += f.y;
            f = __half22float2(hx1); a0.x += f.x; a0.y += f.y;
            f = __half22float2(hy1); a0.z += f.x; a0.w += f.y;
        }
        {   // tail (<8): two fp16 groups of <=4
            __half2 hx0 = hz, hy0 = hz, hx1 = hz, hy1 = hz;
            int n = 0;
            for (; j < p1; j++, n++) {
                int s = __ldg(&g_srcs[j]);
                uint2 u = __ldg((const uint2*)&y[(size_t)s * 128 + c]);
                if (n & 1) {
                    hx1 = __hadd2(hx1, *(__half2*)&u.x);
                    hy1 = __hadd2(hy1, *(__half2*)&u.y);
                } else {
                    hx0 = __hadd2(hx0, *(__half2*)&u.x);
                    hy0 = __hadd2(hy0, *(__half2*)&u.y);
                }
            }
            float2 f;
            f = __half22float2(hx0); a0.x += f.x; a0.y += f.y;
            f = __half22float2(hy0); a0.z += f.x; a0.w += f.y;
            f = __half22float2(hx1); a0.x += f.x; a0.y += f.y;
            f = __half22float2(hy1); a0.z += f.x; a0.w += f.y;
        }
        float4 rb = *(const float4*)&r[(size_t)gw * 128 + c];
        float4 bb = __ldg((const float4*)&bias[c]);
        float4 o;
        o.x = fmaf(a0.x, inv, bb.x + rb.x);
        o.y = fmaf(a0.y, inv, bb.y + rb.y);
        o.z = fmaf(a0.z, inv, bb.z + rb.z);
        o.w = fmaf(a0.w, inv, bb.w + rb.w);
        if (RELU) {
            o.x = fmaxf(o.x, 0.f); o.y = fmaxf(o.y, 0.f);
            o.z = fmaxf(o.z, 0.f); o.w = fmaxf(o.w, 0.f);
        }
        if (sizeof(OUT_T) == 2) {
            __half2 h0 = __floats2half2_rn(o.x, o.y);
            __half2 h1 = __floats2half2_rn(o.z, o.w);
            *(uint2*)&((__half*)out)[(size_t)gw * 128 + c] =
                make_uint2(*(uint32_t*)&h0, *(uint32_t*)&h1);
        } else {
            *(float4*)&((float*)out)[(size_t)gw * 128 + c] = o;
        }
    } else {
        const int c = lane * 2;
        float2 a0 = make_float2(0.f, 0.f);
        int j = p0;
        for (; j + 8 <= p1; j += 8) {
            int ss[8];
#pragma unroll
            for (int q = 0; q < 8; q++) ss[q] = __ldg(&g_srcs[j + q]);
            __half2 v[8];
#pragma unroll
            for (int q = 0; q < 8; q++)
                v[q] = __ldg((const __half2*)&y[(size_t)ss[q] * 64 + c]);
            __half2 h0 = hz, h1 = hz;
#pragma unroll
            for (int q = 0; q < 4; q++) h0 = __hadd2(h0, v[q]);
#pragma unroll
            for (int q = 4; q < 8; q++) h1 = __hadd2(h1, v[q]);
            float2 f;
            f = __half22float2(h0); a0.x += f.x; a0.y += f.y;
            f = __half22float2(h1); a0.x += f.x; a0.y += f.y;
        }
        {   // tail (<8)
            __half2 h0 = hz, h1 = hz;
            int n = 0;
            for (; j < p1; j++, n++) {
                int s = __ldg(&g_srcs[j]);
                __half2 v = __ldg((const __half2*)&y[(size_t)s * 64 + c]);
                if (n & 1) h1 = __hadd2(h1, v);
                else       h0 = __hadd2(h0, v);
            }
            float2 f;
            f = __half22float2(h0); a0.x += f.x; a0.y += f.y;
            f = __half22float2(h1); a0.x += f.x; a0.y += f.y;
        }
        float2 rb = *(const float2*)&r[(size_t)gw * 64 + c];
        float2 bb = __ldg((const float2*)&bias[c]);
        float2 o;
        o.x = fmaf(a0.x, inv, bb.x + rb.x);
        o.y = fmaf(a0.y, inv, bb.y + rb.y);
        if (RELU) { o.x = fmaxf(o.x, 0.f); o.y = fmaxf(o.y, 0.f); }
        if (sizeof(OUT_T) == 2) {
            *(__half2*)&((__half*)out)[(size_t)gw * 64 + c] =
                __floats2half2_rn(o.x, o.y);
        } else {
            *(float2*)&((float*)out)[(size_t)gw * 64 + c] = o;
        }
    }
}

// ---------------- launch ----------------
extern "C" void kernel_launch(void* const* d_in, const int* in_sizes, int n_in,
                              void* d_out, int out_size) {
    const float* x   = (const float*)d_in[0];
    const float* Wl1 = (const float*)d_in[1];
    const float* bl1 = (const float*)d_in[2];
    const float* Wr1 = (const float*)d_in[3];
    const float* Wl2 = (const float*)d_in[4];
    const float* bl2 = (const float*)d_in[5];
    const float* Wr2 = (const float*)d_in[6];
    const int*   ei  = (const int*)d_in[7];
    const int* src = ei;
    const int* dst = ei + N_EDGES;
    float* out = (float*)d_out;

    __half *yhp, *hhp;
    float* r1p;
    cudaGetSymbolAddress((void**)&yhp, g_yh);
    cudaGetSymbolAddress((void**)&hhp, g_hh);
    cudaGetSymbolAddress((void**)&r1p, g_r1);

    constexpr int SMEM = 2 * 128 * 272;   // 69632 B
    cudaFuncSetAttribute(k_fat1,
                         cudaFuncAttributeMaxDynamicSharedMemorySize, SMEM);
    cudaFuncSetAttribute(k_mma2,
                         cudaFuncAttributeMaxDynamicSharedMemorySize, SMEM);

    // prep (hist + x->fp16 + W transpose + flag zero), then fused scan
    k_fath<<<HB + XB + WB, 512>>>(dst, x, Wl1, Wr1, Wl2, Wr2);
    k_scan<<<SCAN_BLOCKS, 1024>>>();

    // layer-1 GEMM blocks first, scatter blocks after, one launch
    k_fat1<<<GEMM1_B + SCAT_B, 512, SMEM>>>(src, dst, yhp, r1p);
    k_agg<128, true, __half><<<(N_NODES + 7) / 8, 256>>>(yhp, r1p, bl1, hhp);

    // layer 2
    k_mma2<<<(N_NODES + 127) / 128, 512, SMEM>>>(yhp, r1p);
    k_agg<64, false, float><<<(N_NODES + 7) / 8, 256>>>(yhp, r1p, bl2, out);
}